// round 17
// baseline (speedup 1.0000x reference)
#include <cuda_runtime.h>
#include <cuda_bf16.h>
#include <math.h>
#include <stdint.h>

// Shapes (fixed)
#define CB 4
#define CT 2048
#define CC 1024
#define CH 16
#define CD 64
#define CM (CB*CT)     // 8192
#define C3 (3*CC)      // 3072

// ---------------- device scratch: EXACT R1 set (proven to pass) ------------
__device__ float g_q[(size_t)CB*CH*CT*CD];
__device__ float g_k[(size_t)CB*CH*CT*CD];
__device__ float g_v[(size_t)CB*CH*CT*CD];
__device__ float g_y[(size_t)CM*CC];
__device__ float g_cos[CT*32];
__device__ float g_sin[CT*32];
// Scratch reuse (no new statics):
//  - qkv weights (split bf16, [N,K]) live in g_y  (dead until attn writes y)
//  - proj weights (split bf16, [N,K]) live in g_q (dead after attn reads q)

// ---------------- PTX helpers (compute_100-safe only) -----------------------
__device__ __forceinline__ uint32_t smem_u32(const void* p) {
    uint32_t a;
    asm("{ .reg .u64 t; cvta.to.shared.u64 t, %1; cvt.u32.u64 %0, t; }" : "=r"(a) : "l"(p));
    return a;
}
#define LDSM4(r0,r1,r2,r3,addr) \
    asm volatile("ldmatrix.sync.aligned.m8n8.x4.shared.b16 {%0,%1,%2,%3}, [%4];" \
                 : "=r"(r0), "=r"(r1), "=r"(r2), "=r"(r3) : "r"(addr))
#define LDSM4T(r0,r1,r2,r3,addr) \
    asm volatile("ldmatrix.sync.aligned.m8n8.x4.trans.shared.b16 {%0,%1,%2,%3}, [%4];" \
                 : "=r"(r0), "=r"(r1), "=r"(r2), "=r"(r3) : "r"(addr))
#define MMA16816(d, a0, a1, a2, a3, b0, b1) \
    asm volatile("mma.sync.aligned.m16n8k16.row.col.f32.bf16.bf16.f32 " \
                 "{%0,%1,%2,%3}, {%4,%5,%6,%7}, {%8,%9}, {%0,%1,%2,%3};" \
                 : "+f"((d)[0]), "+f"((d)[1]), "+f"((d)[2]), "+f"((d)[3]) \
                 : "r"(a0), "r"(a1), "r"(a2), "r"(a3), "r"(b0), "r"(b1))

__device__ __forceinline__ uint32_t pack2(float a, float b) {
    __nv_bfloat16 ha = __float2bfloat16_rn(a);
    __nv_bfloat16 hb = __float2bfloat16_rn(b);
    uint16_t ua = *(uint16_t*)&ha, ub = *(uint16_t*)&hb;
    return (uint32_t)ua | ((uint32_t)ub << 16);
}
__device__ __forceinline__ float bf16_val(float v) {
    __nv_bfloat16 h = __float2bfloat16_rn(v);
    return __bfloat162float(h);
}

// ---------------------------------------------------------------------------
__global__ void rope_table_kernel() {
    int idx = blockIdx.x * blockDim.x + threadIdx.x;
    if (idx >= CT * 32) return;
    int t = idx >> 5;
    int i = idx & 31;
    double dinv = pow(10000.0, -(double)(2 * i) / 64.0);
    float invf = (float)dinv;
    float ang = (float)t * invf;
    g_cos[idx] = cosf(ang);
    g_sin[idx] = sinf(ang);
}

// ---------------------------------------------------------------------------
// W [K=1024, N] -> Whi/Wlo [N, 1024] transpose + split (bf16), written into
// reinterpreted scratch. MODE 0: W_attn -> g_y ; MODE 1: W_proj -> g_q.
// ---------------------------------------------------------------------------
template<int MODE>
__global__ __launch_bounds__(256)
void conv_w_kernel(const float* __restrict__ W) {
    const int N = (MODE == 0) ? C3 : CC;
    __nv_bfloat16* Whi = (MODE == 0) ? (__nv_bfloat16*)g_y : (__nv_bfloat16*)g_q;
    __nv_bfloat16* Wlo = Whi + (size_t)N * CC;
    __shared__ float tile[32][33];
    int tx = threadIdx.x & 31, ty = threadIdx.x >> 5;
    int k0 = blockIdx.x * 32, n0 = blockIdx.y * 32;
#pragma unroll
    for (int i = 0; i < 4; i++)
        tile[ty + 8 * i][tx] = W[(size_t)(k0 + ty + 8 * i) * N + n0 + tx];
    __syncthreads();
#pragma unroll
    for (int i = 0; i < 4; i++) {
        int n = n0 + ty + 8 * i;
        int k = k0 + tx;
        float v = tile[tx][ty + 8 * i];
        __nv_bfloat16 hi = __float2bfloat16_rn(v);
        __nv_bfloat16 lo = __float2bfloat16_rn(v - __bfloat162float(hi));
        Whi[(size_t)n * CC + k] = hi;
        Wlo[(size_t)n * CC + k] = lo;
    }
}

// ---------------------------------------------------------------------------
// Split-bf16 HMMA GEMM v4: pre-split weights (bf16 [N,K] in scratch), so W
// staging is 2x LDG.128 + 2x STS.128. A split stays in-kernel.
// 2 CTAs/SM via __launch_bounds__(512,2); pass-split inner loop (64-reg safe).
// C = Ah.Wh^T + Ah.Wl^T + Al.Wh^T over K=1024 (32 chunks of 32).
// 128x128 block, 16 warps (4x4), warp tile 32x32.
// Smem elem offsets (LDA=40): Ah buf*5120 | Al 10240+ | Wh 20480+ | Wl 30720+
// MODE 0: qkv (A=x, W in g_y) -> RoPE + scatter;
// MODE 1: proj (A=g_y, W in g_q) -> Out.
// ---------------------------------------------------------------------------
#define LDA 40

#define GEMM_STAGE(kc_, b_) do {                                                \
    float4 a0_ = *(const float4*)(Ap + (size_t)ar * CC + (kc_) * 32 + as * 8);  \
    float4 a1_ = *(const float4*)(Ap + (size_t)ar * CC + (kc_) * 32 + as * 8 + 4); \
    uint4 wh_ = *(const uint4*)(Whp + (size_t)ar * CC + (kc_) * 32 + as * 8);   \
    uint4 wl_ = *(const uint4*)(Wlp + (size_t)ar * CC + (kc_) * 32 + as * 8);   \
    __nv_bfloat16* Ah_ = sm_ + (b_) * 5120;                                     \
    __nv_bfloat16* Al_ = sm_ + 10240 + (b_) * 5120;                             \
    __nv_bfloat16* Wh_ = sm_ + 20480 + (b_) * 5120;                             \
    __nv_bfloat16* Wl_ = sm_ + 30720 + (b_) * 5120;                             \
    int off_ = ar * LDA + as * 8;                                               \
    *(uint2*)(Ah_ + off_)     = make_uint2(pack2(a0_.x, a0_.y), pack2(a0_.z, a0_.w)); \
    *(uint2*)(Ah_ + off_ + 4) = make_uint2(pack2(a1_.x, a1_.y), pack2(a1_.z, a1_.w)); \
    *(uint2*)(Al_ + off_)     = make_uint2(                                     \
        pack2(a0_.x - bf16_val(a0_.x), a0_.y - bf16_val(a0_.y)),                \
        pack2(a0_.z - bf16_val(a0_.z), a0_.w - bf16_val(a0_.w)));               \
    *(uint2*)(Al_ + off_ + 4) = make_uint2(                                     \
        pack2(a1_.x - bf16_val(a1_.x), a1_.y - bf16_val(a1_.y)),                \
        pack2(a1_.z - bf16_val(a1_.z), a1_.w - bf16_val(a1_.w)));               \
    *(uint4*)(Wh_ + off_) = wh_;                                                \
    *(uint4*)(Wl_ + off_) = wl_;                                                \
} while (0)

template<int MODE>
__global__ __launch_bounds__(512, 2)
void hmma_gemm_kernel(const float* __restrict__ Asrc,
                      float* __restrict__ Out) {
    extern __shared__ __nv_bfloat16 sm_[];
    const uint32_t uS = smem_u32(sm_);
    const int tid = threadIdx.x;
    const int wid = tid >> 5, lane = tid & 31;
    const int wm = wid >> 2, wn = wid & 3;
    const int m0 = blockIdx.y * 128, n0 = blockIdx.x * 128;
    const float* __restrict__ Ap = (MODE == 0) ? (Asrc + (size_t)m0 * CC)
                                               : (g_y + (size_t)m0 * CC);
    const __nv_bfloat16* Wbase = (MODE == 0) ? (const __nv_bfloat16*)g_y
                                             : (const __nv_bfloat16*)g_q;
    const int N = (MODE == 0) ? C3 : CC;
    const __nv_bfloat16* __restrict__ Whp = Wbase + (size_t)n0 * CC;
    const __nv_bfloat16* __restrict__ Wlp = Wbase + (size_t)N * CC + (size_t)n0 * CC;

    const int ar = tid >> 2;        // stage row 0..127 (A row / W n-row)
    const int as = tid & 3;         // 8-elem segment

    float acc[2][4][4];
#pragma unroll
    for (int mi = 0; mi < 2; mi++)
#pragma unroll
        for (int ni = 0; ni < 4; ni++)
#pragma unroll
            for (int r = 0; r < 4; r++) acc[mi][ni][r] = 0.f;

    const int aOff = (wm * 32 + (lane & 15)) * LDA + (lane >> 4) * 8;
    const int bOff = (wn * 32 + ((lane >> 4) & 1) * 8 + (lane & 7)) * LDA
                     + ((lane >> 3) & 1) * 8;

    GEMM_STAGE(0, 0);
    __syncthreads();

    for (int kc = 0; kc < 32; kc++) {
        const int buf = kc & 1;
        const uint32_t bAh = uS + (uint32_t)(buf * 5120) * 2;
        const uint32_t bAl = uS + (uint32_t)(10240 + buf * 5120) * 2;
        const uint32_t bWh = uS + (uint32_t)(20480 + buf * 5120) * 2;
        const uint32_t bWl = uS + (uint32_t)(30720 + buf * 5120) * 2;

#pragma unroll
        for (int ks = 0; ks < 2; ks++) {
            const uint32_t offB0 = (uint32_t)(bOff + ks * 16) * 2;
            const uint32_t offB1 = (uint32_t)(bOff + ks * 16 + 16 * LDA) * 2;
            uint32_t w0, w1, w2, w3, w4, w5, w6, w7;
            LDSM4(w0, w1, w2, w3, bWh + offB0);
            LDSM4(w4, w5, w6, w7, bWh + offB1);
#pragma unroll
            for (int mi = 0; mi < 2; mi++) {
                uint32_t offA = (uint32_t)(aOff + ks * 16 + mi * 16 * LDA) * 2;
                uint32_t x0, x1, x2, x3;
                LDSM4(x0, x1, x2, x3, bAh + offA);
                MMA16816(acc[mi][0], x0, x1, x2, x3, w0, w1);
                MMA16816(acc[mi][1], x0, x1, x2, x3, w2, w3);
                MMA16816(acc[mi][2], x0, x1, x2, x3, w4, w5);
                MMA16816(acc[mi][3], x0, x1, x2, x3, w6, w7);
                LDSM4(x0, x1, x2, x3, bAl + offA);
                MMA16816(acc[mi][0], x0, x1, x2, x3, w0, w1);
                MMA16816(acc[mi][1], x0, x1, x2, x3, w2, w3);
                MMA16816(acc[mi][2], x0, x1, x2, x3, w4, w5);
                MMA16816(acc[mi][3], x0, x1, x2, x3, w6, w7);
            }
            LDSM4(w0, w1, w2, w3, bWl + offB0);
            LDSM4(w4, w5, w6, w7, bWl + offB1);
#pragma unroll
            for (int mi = 0; mi < 2; mi++) {
                uint32_t offA = (uint32_t)(aOff + ks * 16 + mi * 16 * LDA) * 2;
                uint32_t x0, x1, x2, x3;
                LDSM4(x0, x1, x2, x3, bAh + offA);
                MMA16816(acc[mi][0], x0, x1, x2, x3, w0, w1);
                MMA16816(acc[mi][1], x0, x1, x2, x3, w2, w3);
                MMA16816(acc[mi][2], x0, x1, x2, x3, w4, w5);
                MMA16816(acc[mi][3], x0, x1, x2, x3, w6, w7);
            }
        }

        if (kc + 1 < 32) {
            GEMM_STAGE(kc + 1, buf ^ 1);
        }
        __syncthreads();
    }

    // ------------- epilogue --------------------------------------------------
    const int lrow = lane >> 2;
    const int lcol = (lane & 3) * 2;

#pragma unroll
    for (int mi = 0; mi < 2; mi++) {
#pragma unroll
        for (int rh = 0; rh < 2; rh++) {
            const int r = m0 + wm * 32 + mi * 16 + lrow + rh * 8;
            if (MODE == 1) {
                float* dst = Out + (size_t)r * CC + n0 + wn * 32 + lcol;
#pragma unroll
                for (int ni = 0; ni < 4; ni++)
                    *(float2*)(dst + ni * 8) =
                        make_float2(acc[mi][ni][2 * rh], acc[mi][ni][2 * rh + 1]);
            } else {
                const int bI = r >> 11, t = r & 2047;
                const float* ct = g_cos + t * 32;
                const float* st = g_sin + t * 32;
#pragma unroll
                for (int ni = 0; ni < 4; ni++) {
                    const int cg = n0 + wn * 32 + ni * 8 + lcol;
                    const int seg = cg >> 10;
                    const int cs = cg & 1023;
                    const int h = cs >> 6, d = cs & 63;
                    float* base = (seg == 0) ? g_q : ((seg == 1) ? g_k : g_v);
                    float* dst = base + (((size_t)(bI * CH + h) * CT + t) * CD + d);
                    float x1 = acc[mi][ni][2 * rh], x2 = acc[mi][ni][2 * rh + 1];
                    if (seg == 2) {
                        *(float2*)dst = make_float2(x1, x2);
                    } else {
                        float c = ct[d >> 1], s = st[d >> 1];
                        *(float2*)dst = make_float2(x1 * c - x2 * s, x1 * s + x2 * c);
                    }
                }
            }
        }
    }
}

// ---------------------------------------------------------------------------
// HMMA flash attention v2 (R15 verbatim — proven): V natural layout +
// ldmatrix.trans, exp on MUFU. Writes y fp32 to g_y.
// ---------------------------------------------------------------------------
#define ALDA 72

__global__ __launch_bounds__(256)
void attn_hmma_kernel() {
    extern __shared__ __nv_bfloat16 smA[];
    const uint32_t uS = smem_u32(smA);
    const uint32_t uQh = uS;
    const uint32_t uQl = uS + 9216u * 2;
    const uint32_t uKh = uS + 18432u * 2;
    const uint32_t uKl = uS + 23040u * 2;
    const uint32_t uVh = uS + 27648u * 2;
    const uint32_t uVl = uS + 32256u * 2;

    const int tid = threadIdx.x;
    const int wid = tid >> 5, lane = tid & 31;
    const int bh = blockIdx.y;
    const int qb = gridDim.x - 1 - blockIdx.x;
    const int q0 = qb * 128;
    const float* Qg = g_q + (size_t)bh * CT * CD;
    const float* Kg = g_k + (size_t)bh * CT * CD;
    const float* Vg = g_v + (size_t)bh * CT * CD;

#pragma unroll
    for (int i = 0; i < 8; i++) {
        int idx = tid + 256 * i;
        int row = idx >> 4, seg = idx & 15;
        float4 v = *(const float4*)(Qg + (size_t)(q0 + row) * CD + seg * 4);
        v.x *= 0.125f; v.y *= 0.125f; v.z *= 0.125f; v.w *= 0.125f;
        int off = row * ALDA + seg * 4;
        *(uint2*)(smA + off) = make_uint2(pack2(v.x, v.y), pack2(v.z, v.w));
        *(uint2*)(smA + 9216 + off) = make_uint2(
            pack2(v.x - bf16_val(v.x), v.y - bf16_val(v.y)),
            pack2(v.z - bf16_val(v.z), v.w - bf16_val(v.w)));
    }

    float o[8][4], sacc[8][4];
#pragma unroll
    for (int n = 0; n < 8; n++)
#pragma unroll
        for (int v = 0; v < 4; v++) o[n][v] = 0.f;
    float m0r = -3.0e38f, m1r = -3.0e38f, l0r = 0.f, l1r = 0.f;

    const int aOffQ = (wid * 16 + (lane & 15)) * ALDA + (lane >> 4) * 8;
    const int bOffR = ((lane >> 4) & 1) * 8 + (lane & 7);
    const int bOffC = ((lane >> 3) & 1) * 8;
    const int vOffR = ((lane >> 3) & 1) * 8 + (lane & 7);
    const int vOffC = (lane >> 4) * 8;

    const int ntiles = 2 * qb + 2;
    for (int nt = 0; nt < ntiles; nt++) {
        const int k0 = nt * 64;
        __syncthreads();

#pragma unroll
        for (int i = 0; i < 4; i++) {
            int idx = tid + 256 * i;
            int row = idx >> 4, seg = idx & 15;
            int off = row * ALDA + seg * 4;
            float4 kv = *(const float4*)(Kg + (size_t)(k0 + row) * CD + seg * 4);
            *(uint2*)(smA + 18432 + off) = make_uint2(pack2(kv.x, kv.y), pack2(kv.z, kv.w));
            *(uint2*)(smA + 23040 + off) = make_uint2(
                pack2(kv.x - bf16_val(kv.x), kv.y - bf16_val(kv.y)),
                pack2(kv.z - bf16_val(kv.z), kv.w - bf16_val(kv.w)));
            float4 vv = *(const float4*)(Vg + (size_t)(k0 + row) * CD + seg * 4);
            *(uint2*)(smA + 27648 + off) = make_uint2(pack2(vv.x, vv.y), pack2(vv.z, vv.w));
            *(uint2*)(smA + 32256 + off) = make_uint2(
                pack2(vv.x - bf16_val(vv.x), vv.y - bf16_val(vv.y)),
                pack2(vv.z - bf16_val(vv.z), vv.w - bf16_val(vv.w)));
        }
        __syncthreads();

#pragma unroll
        for (int n = 0; n < 8; n++)
#pragma unroll
            for (int v = 0; v < 4; v++) sacc[n][v] = 0.f;
#pragma unroll
        for (int ks = 0; ks < 4; ks++) {
            uint32_t offA = (uint32_t)(aOffQ + ks * 16) * 2;
            uint32_t ah0, ah1, ah2, ah3, al0, al1, al2, al3;
            LDSM4(ah0, ah1, ah2, ah3, uQh + offA);
            LDSM4(al0, al1, al2, al3, uQl + offA);
#pragma unroll
            for (int nh = 0; nh < 2; nh++) {
                uint32_t kb = (uint32_t)((nh * 32 + bOffR) * ALDA + ks * 16 + bOffC) * 2;
                uint32_t b0, b1, b2, b3, b4, b5, b6, b7;
                LDSM4(b0, b1, b2, b3, uKh + kb);
                LDSM4(b4, b5, b6, b7, uKh + kb + 16 * ALDA * 2);
                MMA16816(sacc[nh * 4 + 0], ah0, ah1, ah2, ah3, b0, b1);
                MMA16816(sacc[nh * 4 + 1], ah0, ah1, ah2, ah3, b2, b3);
                MMA16816(sacc[nh * 4 + 2], ah0, ah1, ah2, ah3, b4, b5);
                MMA16816(sacc[nh * 4 + 3], ah0, ah1, ah2, ah3, b6, b7);
                MMA16816(sacc[nh * 4 + 0], al0, al1, al2, al3, b0, b1);
                MMA16816(sacc[nh * 4 + 1], al0, al1, al2, al3, b2, b3);
                MMA16816(sacc[nh * 4 + 2], al0, al1, al2, al3, b4, b5);
                MMA16816(sacc[nh * 4 + 3], al0, al1, al2, al3, b6, b7);
                LDSM4(b0, b1, b2, b3, uKl + kb);
                LDSM4(b4, b5, b6, b7, uKl + kb + 16 * ALDA * 2);
                MMA16816(sacc[nh * 4 + 0], ah0, ah1, ah2, ah3, b0, b1);
                MMA16816(sacc[nh * 4 + 1], ah0, ah1, ah2, ah3, b2, b3);
                MMA16816(sacc[nh * 4 + 2], ah0, ah1, ah2, ah3, b4, b5);
                MMA16816(sacc[nh * 4 + 3], ah0, ah1, ah2, ah3, b6, b7);
            }
        }

        if (nt >= 2 * qb) {
            const int r0 = q0 + wid * 16 + (lane >> 2);
#pragma unroll
            for (int n = 0; n < 8; n++) {
                int colb = k0 + ((n >> 2) << 5) + ((n & 3) << 3) + (lane & 3) * 2;
#pragma unroll
                for (int v = 0; v < 4; v++) {
                    int col = colb + (v & 1);
                    int row = r0 + (v >> 1) * 8;
                    if (col > row) sacc[n][v] = -1.0e30f;
                }
            }
        }

        float rx0 = -3.0e38f, rx1 = -3.0e38f;
#pragma unroll
        for (int n = 0; n < 8; n++) {
            rx0 = fmaxf(rx0, fmaxf(sacc[n][0], sacc[n][1]));
            rx1 = fmaxf(rx1, fmaxf(sacc[n][2], sacc[n][3]));
        }
        rx0 = fmaxf(rx0, __shfl_xor_sync(0xffffffffu, rx0, 1));
        rx0 = fmaxf(rx0, __shfl_xor_sync(0xffffffffu, rx0, 2));
        rx1 = fmaxf(rx1, __shfl_xor_sync(0xffffffffu, rx1, 1));
        rx1 = fmaxf(rx1, __shfl_xor_sync(0xffffffffu, rx1, 2));
        float mn0 = fmaxf(m0r, rx0), mn1 = fmaxf(m1r, rx1);
        float sf0 = __expf(m0r - mn0), sf1 = __expf(m1r - mn1);
        m0r = mn0; m1r = mn1;
        float rs0 = 0.f, rs1 = 0.f;
#pragma unroll
        for (int n = 0; n < 8; n++) {
            float p0 = __expf(sacc[n][0] - mn0);
            float p1 = __expf(sacc[n][1] - mn0);
            float p2 = __expf(sacc[n][2] - mn1);
            float p3 = __expf(sacc[n][3] - mn1);
            sacc[n][0] = p0; sacc[n][1] = p1; sacc[n][2] = p2; sacc[n][3] = p3;
            rs0 += p0 + p1; rs1 += p2 + p3;
            o[n][0] *= sf0; o[n][1] *= sf0; o[n][2] *= sf1; o[n][3] *= sf1;
        }
        rs0 += __shfl_xor_sync(0xffffffffu, rs0, 1);
        rs0 += __shfl_xor_sync(0xffffffffu, rs0, 2);
        rs1 += __shfl_xor_sync(0xffffffffu, rs1, 1);
        rs1 += __shfl_xor_sync(0xffffffffu, rs1, 2);
        l0r = l0r * sf0 + rs0;
        l1r = l1r * sf1 + rs1;

#pragma unroll
        for (int ks = 0; ks < 4; ks++) {
            float p00 = sacc[2 * ks][0],     p01 = sacc[2 * ks][1];
            float p02 = sacc[2 * ks][2],     p03 = sacc[2 * ks][3];
            float p10 = sacc[2 * ks + 1][0], p11 = sacc[2 * ks + 1][1];
            float p12 = sacc[2 * ks + 1][2], p13 = sacc[2 * ks + 1][3];
            uint32_t ah0 = pack2(p00, p01), ah1 = pack2(p02, p03);
            uint32_t ah2 = pack2(p10, p11), ah3 = pack2(p12, p13);
            uint32_t al0 = pack2(p00 - bf16_val(p00), p01 - bf16_val(p01));
            uint32_t al1 = pack2(p02 - bf16_val(p02), p03 - bf16_val(p03));
            uint32_t al2 = pack2(p10 - bf16_val(p10), p11 - bf16_val(p11));
            uint32_t al3 = pack2(p12 - bf16_val(p12), p13 - bf16_val(p13));
#pragma unroll
            for (int nh = 0; nh < 2; nh++) {
                uint32_t vb = (uint32_t)((ks * 16 + vOffR) * ALDA + nh * 32 + vOffC) * 2;
                uint32_t b0, b1, b2, b3, b4, b5, b6, b7;
                LDSM4T(b0, b1, b2, b3, uVh + vb);
                LDSM4T(b4, b5, b6, b7, uVh + vb + 16 * 2);
                MMA16816(o[nh * 4 + 0], ah0, ah1, ah2, ah3, b0, b1);
                MMA16816(o[nh * 4 + 1], ah0, ah1, ah2, ah3, b2, b3);
                MMA16816(o[nh * 4 + 2], ah0, ah1, ah2, ah3, b4, b5);
                MMA16816(o[nh * 4 + 3], ah0, ah1, ah2, ah3, b6, b7);
                MMA16816(o[nh * 4 + 0], al0, al1, al2, al3, b0, b1);
                MMA16816(o[nh * 4 + 1], al0, al1, al2, al3, b2, b3);
                MMA16816(o[nh * 4 + 2], al0, al1, al2, al3, b4, b5);
                MMA16816(o[nh * 4 + 3], al0, al1, al2, al3, b6, b7);
                LDSM4T(b0, b1, b2, b3, uVl + vb);
                LDSM4T(b4, b5, b6, b7, uVl + vb + 16 * 2);
                MMA16816(o[nh * 4 + 0], ah0, ah1, ah2, ah3, b0, b1);
                MMA16816(o[nh * 4 + 1], ah0, ah1, ah2, ah3, b2, b3);
                MMA16816(o[nh * 4 + 2], ah0, ah1, ah2, ah3, b4, b5);
                MMA16816(o[nh * 4 + 3], ah0, ah1, ah2, ah3, b6, b7);
            }
        }
    }

    const int bI = bh >> 4, h = bh & 15;
    const float inv0 = 1.f / l0r, inv1 = 1.f / l1r;
    const int row0 = q0 + wid * 16 + (lane >> 2);
#pragma unroll
    for (int rh = 0; rh < 2; rh++) {
        int row = row0 + rh * 8;
        float invl = rh ? inv1 : inv0;
        float* dst = g_y + ((size_t)(bI * CT + row)) * CC + h * CD + (lane & 3) * 2;
#pragma unroll
        for (int n = 0; n < 8; n++) {
            int d = ((n >> 2) << 5) + ((n & 3) << 3);
            *(float2*)(dst + d) = make_float2(o[n][2 * rh] * invl, o[n][2 * rh + 1] * invl);
        }
    }
}

// ---------------------------------------------------------------------------
extern "C" void kernel_launch(void* const* d_in, const int* in_sizes, int n_in,
                              void* d_out, int out_size) {
    const float* x      = (const float*)d_in[0];
    const float* W_attn = (const float*)d_in[1];
    const float* W_proj = (const float*)d_in[2];
    float* out = (float*)d_out;
    (void)in_sizes; (void)n_in; (void)out_size;

    static bool attrs_set = false;
    if (!attrs_set) {
        cudaFuncSetAttribute(attn_hmma_kernel,
                             cudaFuncAttributeMaxDynamicSharedMemorySize, 73728);
        cudaFuncSetAttribute(hmma_gemm_kernel<0>,
                             cudaFuncAttributeMaxDynamicSharedMemorySize, 81920);
        cudaFuncSetAttribute(hmma_gemm_kernel<1>,
                             cudaFuncAttributeMaxDynamicSharedMemorySize, 81920);
        attrs_set = true;
    }

    rope_table_kernel<<<(CT * 32 + 255) / 256, 256>>>();

    {   // split W_attn -> g_y scratch (bf16 [N=3072, K=1024] hi|lo)
        dim3 gw(CC / 32, C3 / 32);
        conv_w_kernel<0><<<gw, 256>>>(W_attn);
    }
    {   // qkv: reads x + g_y weights, writes g_q/g_k/g_v (RoPE fused)
        dim3 g1(C3 / 128, CM / 128);
        hmma_gemm_kernel<0><<<g1, 512, 81920>>>(x, nullptr);
    }
    {   // attention: reads g_q/g_k/g_v, writes y -> g_y (overwrites weights)
        dim3 g2(CT / 128, CB * CH);
        attn_hmma_kernel<<<g2, 256, 73728>>>();
    }
    {   // split W_proj -> g_q scratch (dead after attention)
        dim3 gw(CC / 32, CC / 32);
        conv_w_kernel<1><<<gw, 256>>>(W_proj);
    }
    {   // proj: reads g_y + g_q weights, writes out
        dim3 g3(CC / 128, CM / 128);
        hmma_gemm_kernel<1><<<g3, 512, 81920>>>(nullptr, out);
    }
}